// round 14
// baseline (speedup 1.0000x reference)
#include <cuda_runtime.h>
#include <cuda_fp16.h>
#include <cstdint>
#include <math.h>

// Problem constants
#define BB   32
#define TT   32
#define HH   28
#define WW   28
#define FF   48
#define UU   8
#define EPSB 1e-3f
#define NFRAMES (BB*TT)            // 1024
#define FRAME_PIX (HH*WW)          // 784
#define PW   30                    // padded width
#define PROWS (PW*PW)              // 900 padded pixel-rows per frame

// ---------------------------------------------------------------------------
// Warp-MMA helpers
// ---------------------------------------------------------------------------
__device__ __forceinline__ uint32_t smem_u32(const void* p) {
    return (uint32_t)__cvta_generic_to_shared(p);
}
__device__ __forceinline__ void ldmx4(uint32_t a[4], uint32_t addr) {
    asm volatile("ldmatrix.sync.aligned.m8n8.x4.shared.b16 {%0,%1,%2,%3}, [%4];"
                 : "=r"(a[0]), "=r"(a[1]), "=r"(a[2]), "=r"(a[3]) : "r"(addr));
}
__device__ __forceinline__ void mma_fp16(float c[4], const uint32_t a[4],
                                         uint32_t b0, uint32_t b1) {
    asm volatile("mma.sync.aligned.m16n8k16.row.col.f32.f16.f16.f32 "
                 "{%0,%1,%2,%3},{%4,%5,%6,%7},{%8,%9},{%0,%1,%2,%3};"
                 : "+f"(c[0]), "+f"(c[1]), "+f"(c[2]), "+f"(c[3])
                 : "r"(a[0]), "r"(a[1]), "r"(a[2]), "r"(a[3]), "r"(b0), "r"(b1));
}
__device__ __forceinline__ void cpa16(uint32_t dst, const void* src, uint32_t srcbytes) {
    asm volatile("cp.async.cg.shared.global [%0], [%1], 16, %2;"
                 :: "r"(dst), "l"(src), "r"(srcbytes));
}
#define CPA_COMMIT() asm volatile("cp.async.commit_group;" ::: "memory")
#define CPA_WAIT(n)  asm volatile("cp.async.wait_group %0;" :: "n"(n) : "memory")

// ---------------------------------------------------------------------------
// Scratch
// ---------------------------------------------------------------------------
__device__ __align__(16) __half g_a1[NFRAMES * PROWS * FF];
__device__ __align__(16) __half g_a2[NFRAMES * PROWS * FF];
__device__ __align__(16) uint32_t g_bfrag[2][27 * 6 * 64];  // fp16x2 fragments
__device__ float g_feats[NFRAMES * 4 * FF];   // per-(frame,quarter) pooled partials

// ---------------------------------------------------------------------------
// Kernel 0: pre-fragment conv weights (once per run)
// ---------------------------------------------------------------------------
__global__ void prep_kernel(const float* __restrict__ w2,
                            const float* __restrict__ w3)
{
    const float* w = (blockIdx.x == 0) ? w2 : w3;
    uint32_t* dst = g_bfrag[blockIdx.x];
    for (int i = threadIdx.x; i < 162 * 64; i += 256) {
        const int group = i >> 6;
        const int slot  = i & 63;
        const int l     = slot >> 1;
        const int reg   = slot & 1;
        const int tapkc = group / 6;
        const int nt    = group - tapkc * 6;
        const int tap   = tapkc / 3;
        const int kc    = tapkc - tap * 3;
        const int n     = nt * 8 + (l >> 2);
        const int k     = kc * 16 + (l & 3) * 2 + reg * 8;
        const __half h0 = __float2half_rn(w[(tap * FF + k)     * FF + n]);
        const __half h1 = __float2half_rn(w[(tap * FF + k + 1) * FF + n]);
        dst[i] = (uint32_t)__half_as_ushort(h0) | ((uint32_t)__half_as_ushort(h1) << 16);
    }
}

// ---------------------------------------------------------------------------
// Kernel 1: conv1 (C=1 -> 48) + ReLU. Zero-padded smem image, thread =
// (pixel, co-oct): 8 channels per thread, one STG.128 per output unit.
// ---------------------------------------------------------------------------
__global__ void __launch_bounds__(256, 1)
conv1_kernel(const float* __restrict__ x,
             const float* __restrict__ w1,
             const float* __restrict__ b1)
{
    __shared__ float  s_f[PROWS];          // 30x30, zero halo
    __shared__ float2 s_w[9 * 24];
    __shared__ float2 s_b2[24];

    const int frame = blockIdx.x;
    const int tid   = threadIdx.x;

    for (int i = tid; i < PROWS; i += 256) {
        const int r = i / PW, c = i - r * PW;
        float v = 0.f;
        if (r >= 1 && r <= HH && c >= 1 && c <= WW)
            v = x[frame * FRAME_PIX + (r - 1) * WW + (c - 1)];
        s_f[i] = v;
    }
    for (int i = tid; i < 9 * 24; i += 256) s_w[i] = ((const float2*)w1)[i];
    if (tid < 24) s_b2[tid] = ((const float2*)b1)[tid];
    __syncthreads();

    uint32_t* outp = (uint32_t*)(g_a1 + (size_t)frame * PROWS * FF);
    for (int idx = tid; idx < FRAME_PIX * 6; idx += 256) {
        const int p   = idx / 6;
        const int co8 = idx - p * 6;          // octet index 0..5
        const int h   = p / WW;
        const int w   = p - h * WW;
        const int base = h * PW + w;
        float2 acc[4];
        #pragma unroll
        for (int j = 0; j < 4; ++j) acc[j] = s_b2[co8 * 4 + j];
        #pragma unroll
        for (int t = 0; t < 9; ++t) {
            const float v = s_f[base + (t / 3) * PW + (t % 3)];
            #pragma unroll
            for (int j = 0; j < 4; ++j) {
                const float2 fw = s_w[t * 24 + co8 * 4 + j];
                acc[j].x += v * fw.x;
                acc[j].y += v * fw.y;
            }
        }
        uint4 st;
        {
            const __half2 v0 = __floats2half2_rn(fmaxf(acc[0].x, 0.f), fmaxf(acc[0].y, 0.f));
            const __half2 v1 = __floats2half2_rn(fmaxf(acc[1].x, 0.f), fmaxf(acc[1].y, 0.f));
            const __half2 v2 = __floats2half2_rn(fmaxf(acc[2].x, 0.f), fmaxf(acc[2].y, 0.f));
            const __half2 v3 = __floats2half2_rn(fmaxf(acc[3].x, 0.f), fmaxf(acc[3].y, 0.f));
            st.x = *(const uint32_t*)&v0;
            st.y = *(const uint32_t*)&v1;
            st.z = *(const uint32_t*)&v2;
            st.w = *(const uint32_t*)&v3;
        }
        *(uint4*)(outp + ((h + 1) * PW + (w + 1)) * 24 + co8 * 4) = st;
    }
}

// ---------------------------------------------------------------------------
// Kernel 2/3: persistent double-buffered conv48 via mma.sync (fp16, 1 pass).
// 128 threads (4 warps), T_PER_W=4 (B frags amortized over 4 tiles, halving
// B smem traffic vs R11), 2 CTAs/SM (reg budget 256/thread -> no spills).
// Quarter-frame items, 15 tiles + 1 clamped dup slot.
// ---------------------------------------------------------------------------
#define Q_ROWS    225
#define SLAB_ROWS 304
#define A_STRIDE  112
#define A_BYTES   (SLAB_ROWS * A_STRIDE)       // 34048
#define B_BYTES   (27 * 6 * 64 * 4)            // 41472
#define OFF_A0    0
#define OFF_A1    (OFF_A0 + A_BYTES)           // 34048
#define OFF_B     (OFF_A1 + A_BYTES)           // 68096
#define OFF_BI    (OFF_B + B_BYTES)            // 109568
#define CONV_SMEM (OFF_BI + FF * 4)            // 109760
#define MT_MAX    14
#define T_PER_W   4
#define CONV_THR  128
#define GRID_CONV 296                          // 2 CTAs/SM x 148
#define N_ITEMS   (NFRAMES * 4)                // 4096 quarter-frames

__device__ __forceinline__ void issue_slab(uint32_t dst, const __half* __restrict__ in,
                                           int item, int tid)
{
    const int frame = item >> 2;
    const int rbase = (item & 3) * Q_ROWS;
    const char* src = (const char*)(in + (size_t)frame * PROWS * FF);
    for (int i = tid; i < SLAB_ROWS * 7; i += CONV_THR) {
        const int s   = i / 7;
        const int blk = i - s * 7;
        const int r   = rbase - 31 + s;
        bool valid = false;
        if (r >= 0 && r < PROWS && blk < 6) {
            const int rd = r / PW, rm = r - rd * PW;
            valid = (rd >= 1 && rd <= HH && rm >= 1 && rm <= WW);
        }
        const long off = valid ? ((long)r * 96 + blk * 16) : 0;
        cpa16(dst + s * A_STRIDE + blk * 16, src + off, valid ? 16u : 0u);
    }
}

template <int PHASE>
__global__ void __launch_bounds__(CONV_THR, 2)
convmm_kernel(const __half* __restrict__ in,
              const uint32_t* __restrict__ bfrag,
              const float* __restrict__ bias)
{
    extern __shared__ __align__(16) char smem[];
    __shared__ float s_pool[4 * FF];

    const int bid  = blockIdx.x;
    const int tid  = threadIdx.x;
    const int wid  = tid >> 5;                 // 0..3
    const int lane = tid & 31;
    const uint32_t smb = smem_u32(smem);
    const int nItems = (N_ITEMS - bid + GRID_CONV - 1) / GRID_CONV;

    float* s_bias = (float*)(smem + OFF_BI);
    if (tid < FF) s_bias[tid] = bias[tid];

    // Group 0: B fragments + first A slab
    for (int i = tid; i < B_BYTES / 16; i += CONV_THR)
        cpa16(smb + OFF_B + i * 16, (const char*)bfrag + i * 16, 16);
    if (nItems > 0) issue_slab(smb + OFF_A0, in, bid, tid);
    CPA_COMMIT();

    const uint32_t laneoff = (uint32_t)((lane & 15) * A_STRIDE + ((lane >> 4) << 4));
    const uint32_t* s_b = (const uint32_t*)(smem + OFF_B);

    for (int k = 0; k < nItems; ++k) {
        const int item  = bid + GRID_CONV * k;
        const int frame = item >> 2;
        const int rbase = (item & 3) * Q_ROWS;
        const uint32_t abuf = smb + ((k & 1) ? OFF_A1 : OFF_A0);

        if (k + 1 < nItems) {
            issue_slab(smb + ((k & 1) ? OFF_A0 : OFF_A1), in, item + GRID_CONV, tid);
            CPA_COMMIT();
            CPA_WAIT(1);
        } else {
            CPA_WAIT(0);
        }
        __syncthreads();

        // Per-warp tiles: slots wid + 4*i (0..15; slot 15 clamps to 14, skipped)
        int mtv[T_PER_W];
        uint32_t abase[T_PER_W];
        #pragma unroll
        for (int i = 0; i < T_PER_W; ++i) {
            int mt = wid + 4 * i;
            mtv[i] = mt;
            if (mt > MT_MAX) mt = MT_MAX;
            abase[i] = abuf + (uint32_t)((31 + mt * 16) * A_STRIDE) + laneoff;
        }

        float C[T_PER_W][6][4];
        #pragma unroll
        for (int i = 0; i < T_PER_W; ++i)
            #pragma unroll
            for (int nt = 0; nt < 6; ++nt) {
                C[i][nt][0] = 0.f; C[i][nt][1] = 0.f; C[i][nt][2] = 0.f; C[i][nt][3] = 0.f;
            }

        #pragma unroll 1
        for (int g = 0; g < 27; ++g) {
            const int tap = g / 3, kc = g - tap * 3;
            const int dy = tap / 3;
            const int aoff = ((dy - 1) * PW + (tap - dy * 3) - 1) * A_STRIDE + kc * 32;
            uint2 BW[6];
            const int bbase = g * 6 * 64 + lane * 2;
            #pragma unroll
            for (int nt = 0; nt < 6; ++nt)
                BW[nt] = *(const uint2*)(s_b + bbase + nt * 64);
            #pragma unroll
            for (int i = 0; i < T_PER_W; ++i) {
                if (i < 3 || mtv[i] <= MT_MAX) {
                    uint32_t a[4];
                    ldmx4(a, abase[i] + (uint32_t)aoff);
                    #pragma unroll
                    for (int nt = 0; nt < 6; ++nt)
                        mma_fp16(C[i][nt], a, BW[nt].x, BW[nt].y);
                }
            }
        }

        // ---- Epilogue ----
        float pool[6][2];
        if (PHASE == 1) {
            #pragma unroll
            for (int nt = 0; nt < 6; ++nt) { pool[nt][0] = 0.f; pool[nt][1] = 0.f; }
        }

        #pragma unroll
        for (int i = 0; i < T_PER_W; ++i) {
            if (mtv[i] > MT_MAX) continue;
            #pragma unroll
            for (int rh = 0; rh < 2; ++rh) {
                const int r = rbase + mtv[i] * 16 + (lane >> 2) + rh * 8;
                if (PHASE == 0) {
                    if (r < PROWS) {
                        uint32_t* d = (uint32_t*)(g_a2 + ((size_t)frame * PROWS + r) * FF);
                        #pragma unroll
                        for (int nt = 0; nt < 6; ++nt) {
                            const int co = nt * 8 + (lane & 3) * 2;
                            const __half h0 = __float2half_rn(fmaxf(C[i][nt][rh * 2]     + s_bias[co],     0.f));
                            const __half h1 = __float2half_rn(fmaxf(C[i][nt][rh * 2 + 1] + s_bias[co + 1], 0.f));
                            d[co >> 1] = (uint32_t)__half_as_ushort(h0) | ((uint32_t)__half_as_ushort(h1) << 16);
                        }
                    }
                } else {
                    bool valid = false;
                    if ((r - rbase) < Q_ROWS && r < PROWS) {
                        const int rd = r / PW, rm = r - rd * PW;
                        valid = (rd >= 1 && rd <= HH && rm >= 1 && rm <= WW);
                    }
                    if (valid) {
                        #pragma unroll
                        for (int nt = 0; nt < 6; ++nt) {
                            const int co = nt * 8 + (lane & 3) * 2;
                            pool[nt][0] += fmaxf(C[i][nt][rh * 2]     + s_bias[co],     0.f);
                            pool[nt][1] += fmaxf(C[i][nt][rh * 2 + 1] + s_bias[co + 1], 0.f);
                        }
                    }
                }
            }
        }

        if (PHASE == 1) {
            #pragma unroll
            for (int nt = 0; nt < 6; ++nt) {
                #pragma unroll
                for (int e = 0; e < 2; ++e) {
                    float v = pool[nt][e];
                    v += __shfl_xor_sync(0xffffffffu, v, 4);
                    v += __shfl_xor_sync(0xffffffffu, v, 8);
                    v += __shfl_xor_sync(0xffffffffu, v, 16);
                    if ((lane >> 2) == 0)
                        s_pool[wid * FF + nt * 8 + lane * 2 + e] = v;
                }
            }
            __syncthreads();
            if (tid < FF) {
                float s = 0.f;
                #pragma unroll
                for (int ww = 0; ww < 4; ++ww) s += s_pool[ww * FF + tid];
                g_feats[(frame * 4 + (item & 3)) * FF + tid] = s;
            }
        }
        __syncthreads();   // all reads of abuf done before it is refilled
    }
}

// ---------------------------------------------------------------------------
// Kernel 4: LSTM + BN2 + head. 128 threads/block: 4 warps parallelize the
// x-dot precompute (8 timesteps each); warp 0 runs the 8-term recurrence.
// ---------------------------------------------------------------------------
__device__ __forceinline__ float fsig(float x)  { return __fdividef(1.f, 1.f + __expf(-x)); }
__device__ __forceinline__ float ftanh(float x) { return 1.f - __fdividef(2.f, __expf(2.f * x) + 1.f); }

__global__ void __launch_bounds__(128, 1)
lstm_kernel(const float* __restrict__ wf,  const float* __restrict__ bf,
            const float* __restrict__ wi1, const float* __restrict__ bi1,
            const float* __restrict__ wi2, const float* __restrict__ bi2,
            const float* __restrict__ wo,  const float* __restrict__ bo,
            const float* __restrict__ bn1_g, const float* __restrict__ bn1_b,
            const float* __restrict__ bn1_m, const float* __restrict__ bn1_v,
            const float* __restrict__ bn2_g, const float* __restrict__ bn2_b,
            const float* __restrict__ bn2_m, const float* __restrict__ bn2_v,
            const float* __restrict__ w_out, const float* __restrict__ b_out,
            float* __restrict__ out)
{
    __shared__ float s_x[TT][FF];
    __shared__ float s_g[TT][32];
    __shared__ float s_sc1[FF], s_sh1[FF];

    const int b    = blockIdx.x;
    const int tid  = threadIdx.x;
    const int wrp  = tid >> 5;
    const int lane = tid & 31;
    const int u    = lane & 7;

    // every warp holds the full gate-column set (lane -> (gate, u))
    const float* Wg = (lane < 8) ? wf : (lane < 16) ? wi1 : (lane < 24) ? wi2 : wo;
    const float* Bg = (lane < 8) ? bf : (lane < 16) ? bi1 : (lane < 24) ? bi2 : bo;
    float wcol[FF + UU];
    #pragma unroll
    for (int k = 0; k < FF + UU; ++k) wcol[k] = Wg[k * UU + u];
    const float bgate = Bg[u];

    for (int co = tid; co < FF; co += 128) {
        const float sc = bn1_g[co] * rsqrtf(bn1_v[co] + EPSB);
        s_sc1[co] = sc * (1.f / (float)FRAME_PIX);
        s_sh1[co] = bn1_b[co] - bn1_m[co] * sc;
    }
    __syncthreads();

    for (int i = tid; i < TT * FF; i += 128) {
        const int t = i / FF, co = i - t * FF;
        const int fr = (b << 5) + t;
        const float ps = g_feats[(fr * 4 + 0) * FF + co] + g_feats[(fr * 4 + 1) * FF + co]
                       + g_feats[(fr * 4 + 2) * FF + co] + g_feats[(fr * 4 + 3) * FF + co];
        s_x[t][co] = ps * s_sc1[co] + s_sh1[co];
    }
    __syncthreads();

    // parallel x-dot precompute: warp w handles t = w*8 .. w*8+7
    #pragma unroll
    for (int tt = 0; tt < 8; ++tt) {
        const int t = wrp * 8 + tt;
        float a0 = 0.f, a1 = 0.f, a2 = 0.f, a3 = 0.f;
        #pragma unroll
        for (int k = 0; k < FF; k += 4) {
            a0 += s_x[t][k]     * wcol[k];
            a1 += s_x[t][k + 1] * wcol[k + 1];
            a2 += s_x[t][k + 2] * wcol[k + 2];
            a3 += s_x[t][k + 3] * wcol[k + 3];
        }
        s_g[t][lane] = bgate + ((a0 + a1) + (a2 + a3));
    }
    __syncthreads();

    if (wrp == 0) {
        const float sc2  = bn2_g[u] * rsqrtf(bn2_v[u] + EPSB);
        const float coef = sc2 * w_out[u];
        float outc = b_out[0];
        #pragma unroll
        for (int j = 0; j < UU; ++j) {
            const float s2 = bn2_g[j] * rsqrtf(bn2_v[j] + EPSB);
            outc += (bn2_b[j] - bn2_m[j] * s2) * w_out[j];
        }

        float c = 0.f, h = 0.f;
        for (int t = 0; t < TT; ++t) {
            float a = s_g[t][lane];
            #pragma unroll
            for (int j = 0; j < UU; ++j)
                a += __shfl_sync(0xffffffffu, h, j) * wcol[FF + j];

            const float fg = fsig (__shfl_sync(0xffffffffu, a, u));
            const float ig = fsig (__shfl_sync(0xffffffffu, a, u + 8));
            const float gg = ftanh(__shfl_sync(0xffffffffu, a, u + 16));
            const float og = fsig (__shfl_sync(0xffffffffu, a, u + 24));
            c = fg * c + ig * gg;
            h = og * ftanh(c);

            float p = h * coef;
            p += __shfl_xor_sync(0xffffffffu, p, 1);
            p += __shfl_xor_sync(0xffffffffu, p, 2);
            p += __shfl_xor_sync(0xffffffffu, p, 4);
            if (lane == 0) out[(b << 5) + t] = p + outc;
        }
    }
}

// ---------------------------------------------------------------------------
// Launch
// ---------------------------------------------------------------------------
extern "C" void kernel_launch(void* const* d_in, const int* in_sizes, int n_in,
                              void* d_out, int out_size)
{
    const float* x     = (const float*)d_in[0];
    const float* w1    = (const float*)d_in[1];
    const float* b1    = (const float*)d_in[2];
    const float* w2    = (const float*)d_in[3];
    const float* b2    = (const float*)d_in[4];
    const float* w3    = (const float*)d_in[5];
    const float* b3    = (const float*)d_in[6];
    const float* bn1_g = (const float*)d_in[7];
    const float* bn1_b = (const float*)d_in[8];
    const float* bn1_m = (const float*)d_in[9];
    const float* bn1_v = (const float*)d_in[10];
    const float* wf    = (const float*)d_in[11];
    const float* bf    = (const float*)d_in[12];
    const float* wi1   = (const float*)d_in[13];
    const float* bi1   = (const float*)d_in[14];
    const float* wi2   = (const float*)d_in[15];
    const float* bi2   = (const float*)d_in[16];
    const float* wo    = (const float*)d_in[17];
    const float* bo    = (const float*)d_in[18];
    const float* bn2_g = (const float*)d_in[19];
    const float* bn2_b = (const float*)d_in[20];
    const float* bn2_m = (const float*)d_in[21];
    const float* bn2_v = (const float*)d_in[22];
    const float* w_out = (const float*)d_in[23];
    const float* b_out = (const float*)d_in[24];
    float* out = (float*)d_out;

    cudaFuncSetAttribute(convmm_kernel<0>, cudaFuncAttributeMaxDynamicSharedMemorySize, CONV_SMEM);
    cudaFuncSetAttribute(convmm_kernel<1>, cudaFuncAttributeMaxDynamicSharedMemorySize, CONV_SMEM);

    __half *a1 = nullptr, *a2 = nullptr;
    uint32_t* bfrag = nullptr;
    cudaGetSymbolAddress((void**)&a1, g_a1);
    cudaGetSymbolAddress((void**)&a2, g_a2);
    cudaGetSymbolAddress((void**)&bfrag, g_bfrag);

    prep_kernel<<<2, 256>>>(w2, w3);
    conv1_kernel<<<NFRAMES, 256>>>(x, w1, b1);
    convmm_kernel<0><<<GRID_CONV, CONV_THR, CONV_SMEM>>>(a1, bfrag, b2);
    convmm_kernel<1><<<GRID_CONV, CONV_THR, CONV_SMEM>>>(a2, bfrag + 27 * 6 * 64, b3);
    lstm_kernel<<<BB, 128>>>(wf, bf, wi1, bi1, wi2, bi2, wo, bo,
                             bn1_g, bn1_b, bn1_m, bn1_v,
                             bn2_g, bn2_b, bn2_m, bn2_v,
                             w_out, b_out, out);
}

// round 15
// speedup vs baseline: 1.0688x; 1.0688x over previous
#include <cuda_runtime.h>
#include <cuda_fp16.h>
#include <cstdint>
#include <math.h>

// Problem constants
#define BB   32
#define TT   32
#define HH   28
#define WW   28
#define FF   48
#define UU   8
#define EPSB 1e-3f
#define NFRAMES (BB*TT)            // 1024
#define FRAME_PIX (HH*WW)          // 784
#define PW   30                    // padded width
#define PROWS (PW*PW)              // 900 padded pixel-rows per frame

// ---------------------------------------------------------------------------
// Warp-MMA helpers
// ---------------------------------------------------------------------------
__device__ __forceinline__ uint32_t smem_u32(const void* p) {
    return (uint32_t)__cvta_generic_to_shared(p);
}
__device__ __forceinline__ void ldmx4(uint32_t a[4], uint32_t addr) {
    asm volatile("ldmatrix.sync.aligned.m8n8.x4.shared.b16 {%0,%1,%2,%3}, [%4];"
                 : "=r"(a[0]), "=r"(a[1]), "=r"(a[2]), "=r"(a[3]) : "r"(addr));
}
__device__ __forceinline__ void mma_fp16(float c[4], const uint32_t a[4],
                                         uint32_t b0, uint32_t b1) {
    asm volatile("mma.sync.aligned.m16n8k16.row.col.f32.f16.f16.f32 "
                 "{%0,%1,%2,%3},{%4,%5,%6,%7},{%8,%9},{%0,%1,%2,%3};"
                 : "+f"(c[0]), "+f"(c[1]), "+f"(c[2]), "+f"(c[3])
                 : "r"(a[0]), "r"(a[1]), "r"(a[2]), "r"(a[3]), "r"(b0), "r"(b1));
}
__device__ __forceinline__ void cpa16(uint32_t dst, const void* src, uint32_t srcbytes) {
    asm volatile("cp.async.cg.shared.global [%0], [%1], 16, %2;"
                 :: "r"(dst), "l"(src), "r"(srcbytes));
}
#define CPA_COMMIT() asm volatile("cp.async.commit_group;" ::: "memory")
#define CPA_WAIT(n)  asm volatile("cp.async.wait_group %0;" :: "n"(n) : "memory")

// ---------------------------------------------------------------------------
// Scratch
// ---------------------------------------------------------------------------
__device__ __align__(16) __half g_a1[NFRAMES * PROWS * FF];
__device__ __align__(16) __half g_a2[NFRAMES * PROWS * FF];
__device__ __align__(16) uint32_t g_bfrag[2][27 * 6 * 64];  // fp16x2 fragments
__device__ float g_feats[NFRAMES * 4 * FF];   // per-(frame,quarter) pooled partials

// ---------------------------------------------------------------------------
// Kernel 0: pre-fragment conv weights (once per run)
// ---------------------------------------------------------------------------
__global__ void prep_kernel(const float* __restrict__ w2,
                            const float* __restrict__ w3)
{
    const float* w = (blockIdx.x == 0) ? w2 : w3;
    uint32_t* dst = g_bfrag[blockIdx.x];
    for (int i = threadIdx.x; i < 162 * 64; i += 256) {
        const int group = i >> 6;
        const int slot  = i & 63;
        const int l     = slot >> 1;
        const int reg   = slot & 1;
        const int tapkc = group / 6;
        const int nt    = group - tapkc * 6;
        const int tap   = tapkc / 3;
        const int kc    = tapkc - tap * 3;
        const int n     = nt * 8 + (l >> 2);
        const int k     = kc * 16 + (l & 3) * 2 + reg * 8;
        const __half h0 = __float2half_rn(w[(tap * FF + k)     * FF + n]);
        const __half h1 = __float2half_rn(w[(tap * FF + k + 1) * FF + n]);
        dst[i] = (uint32_t)__half_as_ushort(h0) | ((uint32_t)__half_as_ushort(h1) << 16);
    }
}

// ---------------------------------------------------------------------------
// Kernel 1: conv1 (C=1 -> 48) + ReLU. Zero-padded smem image, thread =
// (pixel, co-oct): 8 channels per thread, one STG.128 per output unit.
// ---------------------------------------------------------------------------
__global__ void __launch_bounds__(256, 1)
conv1_kernel(const float* __restrict__ x,
             const float* __restrict__ w1,
             const float* __restrict__ b1)
{
    __shared__ float  s_f[PROWS];          // 30x30, zero halo
    __shared__ float2 s_w[9 * 24];
    __shared__ float2 s_b2[24];

    const int frame = blockIdx.x;
    const int tid   = threadIdx.x;

    for (int i = tid; i < PROWS; i += 256) {
        const int r = i / PW, c = i - r * PW;
        float v = 0.f;
        if (r >= 1 && r <= HH && c >= 1 && c <= WW)
            v = x[frame * FRAME_PIX + (r - 1) * WW + (c - 1)];
        s_f[i] = v;
    }
    for (int i = tid; i < 9 * 24; i += 256) s_w[i] = ((const float2*)w1)[i];
    if (tid < 24) s_b2[tid] = ((const float2*)b1)[tid];
    __syncthreads();

    uint32_t* outp = (uint32_t*)(g_a1 + (size_t)frame * PROWS * FF);
    for (int idx = tid; idx < FRAME_PIX * 6; idx += 256) {
        const int p   = idx / 6;
        const int co8 = idx - p * 6;          // octet index 0..5
        const int h   = p / WW;
        const int w   = p - h * WW;
        const int base = h * PW + w;
        float2 acc[4];
        #pragma unroll
        for (int j = 0; j < 4; ++j) acc[j] = s_b2[co8 * 4 + j];
        #pragma unroll
        for (int t = 0; t < 9; ++t) {
            const float v = s_f[base + (t / 3) * PW + (t % 3)];
            #pragma unroll
            for (int j = 0; j < 4; ++j) {
                const float2 fw = s_w[t * 24 + co8 * 4 + j];
                acc[j].x += v * fw.x;
                acc[j].y += v * fw.y;
            }
        }
        uint4 st;
        {
            const __half2 v0 = __floats2half2_rn(fmaxf(acc[0].x, 0.f), fmaxf(acc[0].y, 0.f));
            const __half2 v1 = __floats2half2_rn(fmaxf(acc[1].x, 0.f), fmaxf(acc[1].y, 0.f));
            const __half2 v2 = __floats2half2_rn(fmaxf(acc[2].x, 0.f), fmaxf(acc[2].y, 0.f));
            const __half2 v3 = __floats2half2_rn(fmaxf(acc[3].x, 0.f), fmaxf(acc[3].y, 0.f));
            st.x = *(const uint32_t*)&v0;
            st.y = *(const uint32_t*)&v1;
            st.z = *(const uint32_t*)&v2;
            st.w = *(const uint32_t*)&v3;
        }
        *(uint4*)(outp + ((h + 1) * PW + (w + 1)) * 24 + co8 * 4) = st;
    }
}

// ---------------------------------------------------------------------------
// Kernel 2/3: persistent double-buffered conv48 via mma.sync (fp16, 1 pass).
// R11 config (proven 132 us/layer): 256 threads / 8 warps, T_PER_W=2,
// 2 CTAs/SM via quarter-frame items (smem 107 KB/CTA).
// ---------------------------------------------------------------------------
#define Q_ROWS    225
#define SLAB_ROWS 304
#define A_STRIDE  112
#define A_BYTES   (SLAB_ROWS * A_STRIDE)       // 34048
#define B_BYTES   (27 * 6 * 64 * 4)            // 41472
#define OFF_A0    0
#define OFF_A1    (OFF_A0 + A_BYTES)           // 34048
#define OFF_B     (OFF_A1 + A_BYTES)           // 68096
#define OFF_BI    (OFF_B + B_BYTES)            // 109568
#define CONV_SMEM (OFF_BI + FF * 4)            // 109760
#define MT_MAX    14
#define T_PER_W   2
#define GRID_CONV 296                          // 2 CTAs/SM x 148
#define N_ITEMS   (NFRAMES * 4)                // 4096 quarter-frames

__device__ __forceinline__ void issue_slab(uint32_t dst, const __half* __restrict__ in,
                                           int item, int tid)
{
    const int frame = item >> 2;
    const int rbase = (item & 3) * Q_ROWS;
    const char* src = (const char*)(in + (size_t)frame * PROWS * FF);
    for (int i = tid; i < SLAB_ROWS * 7; i += 256) {
        const int s   = i / 7;
        const int blk = i - s * 7;
        const int r   = rbase - 31 + s;
        bool valid = false;
        if (r >= 0 && r < PROWS && blk < 6) {
            const int rd = r / PW, rm = r - rd * PW;
            valid = (rd >= 1 && rd <= HH && rm >= 1 && rm <= WW);
        }
        const long off = valid ? ((long)r * 96 + blk * 16) : 0;
        cpa16(dst + s * A_STRIDE + blk * 16, src + off, valid ? 16u : 0u);
    }
}

template <int PHASE>
__global__ void __launch_bounds__(256, 2)
convmm_kernel(const __half* __restrict__ in,
              const uint32_t* __restrict__ bfrag,
              const float* __restrict__ bias)
{
    extern __shared__ __align__(16) char smem[];
    __shared__ float s_pool[8 * FF];

    const int bid  = blockIdx.x;
    const int tid  = threadIdx.x;
    const int wid  = tid >> 5;
    const int lane = tid & 31;
    const uint32_t smb = smem_u32(smem);
    const int nItems = (N_ITEMS - bid + GRID_CONV - 1) / GRID_CONV;

    float* s_bias = (float*)(smem + OFF_BI);
    if (tid < FF) s_bias[tid] = bias[tid];

    // Group 0: B fragments + first A slab
    for (int i = tid; i < B_BYTES / 16; i += 256)
        cpa16(smb + OFF_B + i * 16, (const char*)bfrag + i * 16, 16);
    if (nItems > 0) issue_slab(smb + OFF_A0, in, bid, tid);
    CPA_COMMIT();

    const uint32_t laneoff = (uint32_t)((lane & 15) * A_STRIDE + ((lane >> 4) << 4));
    const uint32_t* s_b = (const uint32_t*)(smem + OFF_B);

    for (int k = 0; k < nItems; ++k) {
        const int item  = bid + GRID_CONV * k;
        const int frame = item >> 2;
        const int rbase = (item & 3) * Q_ROWS;
        const uint32_t abuf = smb + ((k & 1) ? OFF_A1 : OFF_A0);

        if (k + 1 < nItems) {
            issue_slab(smb + ((k & 1) ? OFF_A0 : OFF_A1), in, item + GRID_CONV, tid);
            CPA_COMMIT();
            CPA_WAIT(1);
        } else {
            CPA_WAIT(0);
        }
        __syncthreads();

        int mtv[T_PER_W];
        uint32_t abase[T_PER_W];
        #pragma unroll
        for (int i = 0; i < T_PER_W; ++i) {
            int mt = wid + 8 * i;
            mtv[i] = mt;
            if (mt > MT_MAX) mt = MT_MAX;
            abase[i] = abuf + (uint32_t)((31 + mt * 16) * A_STRIDE) + laneoff;
        }

        float C[T_PER_W][6][4];
        #pragma unroll
        for (int i = 0; i < T_PER_W; ++i)
            #pragma unroll
            for (int nt = 0; nt < 6; ++nt) {
                C[i][nt][0] = 0.f; C[i][nt][1] = 0.f; C[i][nt][2] = 0.f; C[i][nt][3] = 0.f;
            }

        #pragma unroll 1
        for (int tap = 0; tap < 9; ++tap) {
            const int dy = tap / 3;
            const int aoff0 = ((dy - 1) * PW + (tap - dy * 3) - 1) * A_STRIDE;
            #pragma unroll
            for (int kc = 0; kc < 3; ++kc) {
                uint2 BW[6];
                const int bbase = ((tap * 3 + kc) * 6) * 64 + lane * 2;
                #pragma unroll
                for (int nt = 0; nt < 6; ++nt)
                    BW[nt] = *(const uint2*)(s_b + bbase + nt * 64);
                #pragma unroll
                for (int i = 0; i < T_PER_W; ++i) {
                    if (i == 0 || mtv[i] <= MT_MAX) {
                        uint32_t a[4];
                        ldmx4(a, abase[i] + (uint32_t)(aoff0 + kc * 32));
                        #pragma unroll
                        for (int nt = 0; nt < 6; ++nt)
                            mma_fp16(C[i][nt], a, BW[nt].x, BW[nt].y);
                    }
                }
            }
        }

        // ---- Epilogue ----
        float pool[6][2];
        if (PHASE == 1) {
            #pragma unroll
            for (int nt = 0; nt < 6; ++nt) { pool[nt][0] = 0.f; pool[nt][1] = 0.f; }
        }

        #pragma unroll
        for (int i = 0; i < T_PER_W; ++i) {
            if (mtv[i] > MT_MAX) continue;
            #pragma unroll
            for (int rh = 0; rh < 2; ++rh) {
                const int r = rbase + mtv[i] * 16 + (lane >> 2) + rh * 8;
                if (PHASE == 0) {
                    if (r < PROWS) {
                        uint32_t* d = (uint32_t*)(g_a2 + ((size_t)frame * PROWS + r) * FF);
                        #pragma unroll
                        for (int nt = 0; nt < 6; ++nt) {
                            const int co = nt * 8 + (lane & 3) * 2;
                            const __half h0 = __float2half_rn(fmaxf(C[i][nt][rh * 2]     + s_bias[co],     0.f));
                            const __half h1 = __float2half_rn(fmaxf(C[i][nt][rh * 2 + 1] + s_bias[co + 1], 0.f));
                            d[co >> 1] = (uint32_t)__half_as_ushort(h0) | ((uint32_t)__half_as_ushort(h1) << 16);
                        }
                    }
                } else {
                    bool valid = false;
                    if ((r - rbase) < Q_ROWS && r < PROWS) {
                        const int rd = r / PW, rm = r - rd * PW;
                        valid = (rd >= 1 && rd <= HH && rm >= 1 && rm <= WW);
                    }
                    if (valid) {
                        #pragma unroll
                        for (int nt = 0; nt < 6; ++nt) {
                            const int co = nt * 8 + (lane & 3) * 2;
                            pool[nt][0] += fmaxf(C[i][nt][rh * 2]     + s_bias[co],     0.f);
                            pool[nt][1] += fmaxf(C[i][nt][rh * 2 + 1] + s_bias[co + 1], 0.f);
                        }
                    }
                }
            }
        }

        if (PHASE == 1) {
            #pragma unroll
            for (int nt = 0; nt < 6; ++nt) {
                #pragma unroll
                for (int e = 0; e < 2; ++e) {
                    float v = pool[nt][e];
                    v += __shfl_xor_sync(0xffffffffu, v, 4);
                    v += __shfl_xor_sync(0xffffffffu, v, 8);
                    v += __shfl_xor_sync(0xffffffffu, v, 16);
                    if ((lane >> 2) == 0)
                        s_pool[wid * FF + nt * 8 + lane * 2 + e] = v;
                }
            }
            __syncthreads();
            if (tid < FF) {
                float s = 0.f;
                #pragma unroll
                for (int ww = 0; ww < 8; ++ww) s += s_pool[ww * FF + tid];
                g_feats[(frame * 4 + (item & 3)) * FF + tid] = s;
            }
        }
        __syncthreads();   // all reads of abuf done before it is refilled
    }
}

// ---------------------------------------------------------------------------
// Kernel 4: LSTM + BN2 + head. 128 threads/block: 4 warps parallelize the
// x-dot precompute (8 timesteps each); warp 0 runs the 8-term recurrence.
// (Measured ~8 us in R14.)
// ---------------------------------------------------------------------------
__device__ __forceinline__ float fsig(float x)  { return __fdividef(1.f, 1.f + __expf(-x)); }
__device__ __forceinline__ float ftanh(float x) { return 1.f - __fdividef(2.f, __expf(2.f * x) + 1.f); }

__global__ void __launch_bounds__(128, 1)
lstm_kernel(const float* __restrict__ wf,  const float* __restrict__ bf,
            const float* __restrict__ wi1, const float* __restrict__ bi1,
            const float* __restrict__ wi2, const float* __restrict__ bi2,
            const float* __restrict__ wo,  const float* __restrict__ bo,
            const float* __restrict__ bn1_g, const float* __restrict__ bn1_b,
            const float* __restrict__ bn1_m, const float* __restrict__ bn1_v,
            const float* __restrict__ bn2_g, const float* __restrict__ bn2_b,
            const float* __restrict__ bn2_m, const float* __restrict__ bn2_v,
            const float* __restrict__ w_out, const float* __restrict__ b_out,
            float* __restrict__ out)
{
    __shared__ float s_x[TT][FF];
    __shared__ float s_g[TT][32];
    __shared__ float s_sc1[FF], s_sh1[FF];

    const int b    = blockIdx.x;
    const int tid  = threadIdx.x;
    const int wrp  = tid >> 5;
    const int lane = tid & 31;
    const int u    = lane & 7;

    const float* Wg = (lane < 8) ? wf : (lane < 16) ? wi1 : (lane < 24) ? wi2 : wo;
    const float* Bg = (lane < 8) ? bf : (lane < 16) ? bi1 : (lane < 24) ? bi2 : bo;
    float wcol[FF + UU];
    #pragma unroll
    for (int k = 0; k < FF + UU; ++k) wcol[k] = Wg[k * UU + u];
    const float bgate = Bg[u];

    for (int co = tid; co < FF; co += 128) {
        const float sc = bn1_g[co] * rsqrtf(bn1_v[co] + EPSB);
        s_sc1[co] = sc * (1.f / (float)FRAME_PIX);
        s_sh1[co] = bn1_b[co] - bn1_m[co] * sc;
    }
    __syncthreads();

    for (int i = tid; i < TT * FF; i += 128) {
        const int t = i / FF, co = i - t * FF;
        const int fr = (b << 5) + t;
        const float ps = g_feats[(fr * 4 + 0) * FF + co] + g_feats[(fr * 4 + 1) * FF + co]
                       + g_feats[(fr * 4 + 2) * FF + co] + g_feats[(fr * 4 + 3) * FF + co];
        s_x[t][co] = ps * s_sc1[co] + s_sh1[co];
    }
    __syncthreads();

    #pragma unroll
    for (int tt = 0; tt < 8; ++tt) {
        const int t = wrp * 8 + tt;
        float a0 = 0.f, a1 = 0.f, a2 = 0.f, a3 = 0.f;
        #pragma unroll
        for (int k = 0; k < FF; k += 4) {
            a0 += s_x[t][k]     * wcol[k];
            a1 += s_x[t][k + 1] * wcol[k + 1];
            a2 += s_x[t][k + 2] * wcol[k + 2];
            a3 += s_x[t][k + 3] * wcol[k + 3];
        }
        s_g[t][lane] = bgate + ((a0 + a1) + (a2 + a3));
    }
    __syncthreads();

    if (wrp == 0) {
        const float sc2  = bn2_g[u] * rsqrtf(bn2_v[u] + EPSB);
        const float coef = sc2 * w_out[u];
        float outc = b_out[0];
        #pragma unroll
        for (int j = 0; j < UU; ++j) {
            const float s2 = bn2_g[j] * rsqrtf(bn2_v[j] + EPSB);
            outc += (bn2_b[j] - bn2_m[j] * s2) * w_out[j];
        }

        float c = 0.f, h = 0.f;
        for (int t = 0; t < TT; ++t) {
            float a = s_g[t][lane];
            #pragma unroll
            for (int j = 0; j < UU; ++j)
                a += __shfl_sync(0xffffffffu, h, j) * wcol[FF + j];

            const float fg = fsig (__shfl_sync(0xffffffffu, a, u));
            const float ig = fsig (__shfl_sync(0xffffffffu, a, u + 8));
            const float gg = ftanh(__shfl_sync(0xffffffffu, a, u + 16));
            const float og = fsig (__shfl_sync(0xffffffffu, a, u + 24));
            c = fg * c + ig * gg;
            h = og * ftanh(c);

            float p = h * coef;
            p += __shfl_xor_sync(0xffffffffu, p, 1);
            p += __shfl_xor_sync(0xffffffffu, p, 2);
            p += __shfl_xor_sync(0xffffffffu, p, 4);
            if (lane == 0) out[(b << 5) + t] = p + outc;
        }
    }
}

// ---------------------------------------------------------------------------
// Launch
// ---------------------------------------------------------------------------
extern "C" void kernel_launch(void* const* d_in, const int* in_sizes, int n_in,
                              void* d_out, int out_size)
{
    const float* x     = (const float*)d_in[0];
    const float* w1    = (const float*)d_in[1];
    const float* b1    = (const float*)d_in[2];
    const float* w2    = (const float*)d_in[3];
    const float* b2    = (const float*)d_in[4];
    const float* w3    = (const float*)d_in[5];
    const float* b3    = (const float*)d_in[6];
    const float* bn1_g = (const float*)d_in[7];
    const float* bn1_b = (const float*)d_in[8];
    const float* bn1_m = (const float*)d_in[9];
    const float* bn1_v = (const float*)d_in[10];
    const float* wf    = (const float*)d_in[11];
    const float* bf    = (const float*)d_in[12];
    const float* wi1   = (const float*)d_in[13];
    const float* bi1   = (const float*)d_in[14];
    const float* wi2   = (const float*)d_in[15];
    const float* bi2   = (const float*)d_in[16];
    const float* wo    = (const float*)d_in[17];
    const float* bo    = (const float*)d_in[18];
    const float* bn2_g = (const float*)d_in[19];
    const float* bn2_b = (const float*)d_in[20];
    const float* bn2_m = (const float*)d_in[21];
    const float* bn2_v = (const float*)d_in[22];
    const float* w_out = (const float*)d_in[23];
    const float* b_out = (const float*)d_in[24];
    float* out = (float*)d_out;

    cudaFuncSetAttribute(convmm_kernel<0>, cudaFuncAttributeMaxDynamicSharedMemorySize, CONV_SMEM);
    cudaFuncSetAttribute(convmm_kernel<1>, cudaFuncAttributeMaxDynamicSharedMemorySize, CONV_SMEM);

    __half *a1 = nullptr, *a2 = nullptr;
    uint32_t* bfrag = nullptr;
    cudaGetSymbolAddress((void**)&a1, g_a1);
    cudaGetSymbolAddress((void**)&a2, g_a2);
    cudaGetSymbolAddress((void**)&bfrag, g_bfrag);

    prep_kernel<<<2, 256>>>(w2, w3);
    conv1_kernel<<<NFRAMES, 256>>>(x, w1, b1);
    convmm_kernel<0><<<GRID_CONV, 256, CONV_SMEM>>>(a1, bfrag, b2);
    convmm_kernel<1><<<GRID_CONV, 256, CONV_SMEM>>>(a2, bfrag + 27 * 6 * 64, b3);
    lstm_kernel<<<BB, 128>>>(wf, bf, wi1, bi1, wi2, bi2, wo, bo,
                             bn1_g, bn1_b, bn1_m, bn1_v,
                             bn2_g, bn2_b, bn2_m, bn2_v,
                             w_out, b_out, out);
}

// round 16
// speedup vs baseline: 1.1164x; 1.0445x over previous
#include <cuda_runtime.h>
#include <cuda_fp16.h>
#include <cstdint>
#include <math.h>

// Problem constants
#define BB   32
#define TT   32
#define HH   28
#define WW   28
#define FF   48
#define UU   8
#define EPSB 1e-3f
#define NFRAMES (BB*TT)            // 1024
#define FRAME_PIX (HH*WW)          // 784
#define PW   30                    // padded width
#define PROWS (PW*PW)              // 900 padded pixel-rows per frame

// ---------------------------------------------------------------------------
// Warp-MMA helpers
// ---------------------------------------------------------------------------
__device__ __forceinline__ uint32_t smem_u32(const void* p) {
    return (uint32_t)__cvta_generic_to_shared(p);
}
__device__ __forceinline__ void ldmx4(uint32_t a[4], uint32_t addr) {
    asm volatile("ldmatrix.sync.aligned.m8n8.x4.shared.b16 {%0,%1,%2,%3}, [%4];"
                 : "=r"(a[0]), "=r"(a[1]), "=r"(a[2]), "=r"(a[3]) : "r"(addr));
}
__device__ __forceinline__ void mma_fp16(float c[4], const uint32_t a[4],
                                         uint32_t b0, uint32_t b1) {
    asm volatile("mma.sync.aligned.m16n8k16.row.col.f32.f16.f16.f32 "
                 "{%0,%1,%2,%3},{%4,%5,%6,%7},{%8,%9},{%0,%1,%2,%3};"
                 : "+f"(c[0]), "+f"(c[1]), "+f"(c[2]), "+f"(c[3])
                 : "r"(a[0]), "r"(a[1]), "r"(a[2]), "r"(a[3]), "r"(b0), "r"(b1));
}
__device__ __forceinline__ void cpa16(uint32_t dst, const void* src, uint32_t srcbytes) {
    asm volatile("cp.async.cg.shared.global [%0], [%1], 16, %2;"
                 :: "r"(dst), "l"(src), "r"(srcbytes));
}
#define CPA_COMMIT() asm volatile("cp.async.commit_group;" ::: "memory")
#define CPA_WAIT(n)  asm volatile("cp.async.wait_group %0;" :: "n"(n) : "memory")

// ---------------------------------------------------------------------------
// Scratch
// ---------------------------------------------------------------------------
__device__ __align__(16) __half g_a1[NFRAMES * PROWS * FF];
__device__ __align__(16) __half g_a2[NFRAMES * PROWS * FF];
__device__ __align__(16) uint32_t g_bfrag[2][27 * 6 * 64];  // fp16x2 fragments
__device__ float g_feats[NFRAMES * 4 * FF];   // per-(frame,quarter) pooled partials

// ---------------------------------------------------------------------------
// Kernel 0: pre-fragment conv weights (once per run)
// ---------------------------------------------------------------------------
__global__ void prep_kernel(const float* __restrict__ w2,
                            const float* __restrict__ w3)
{
    const float* w = (blockIdx.x == 0) ? w2 : w3;
    uint32_t* dst = g_bfrag[blockIdx.x];
    for (int i = threadIdx.x; i < 162 * 64; i += 256) {
        const int group = i >> 6;
        const int slot  = i & 63;
        const int l     = slot >> 1;
        const int reg   = slot & 1;
        const int tapkc = group / 6;
        const int nt    = group - tapkc * 6;
        const int tap   = tapkc / 3;
        const int kc    = tapkc - tap * 3;
        const int n     = nt * 8 + (l >> 2);
        const int k     = kc * 16 + (l & 3) * 2 + reg * 8;
        const __half h0 = __float2half_rn(w[(tap * FF + k)     * FF + n]);
        const __half h1 = __float2half_rn(w[(tap * FF + k + 1) * FF + n]);
        dst[i] = (uint32_t)__half_as_ushort(h0) | ((uint32_t)__half_as_ushort(h1) << 16);
    }
}

// ---------------------------------------------------------------------------
// Kernel 1: conv1 (C=1 -> 48) + ReLU. R11 version (measured fastest):
// zero-padded smem image, thread = (pixel, co-pair), float2 weights,
// half2 4B stores.
// ---------------------------------------------------------------------------
__global__ void __launch_bounds__(256, 1)
conv1_kernel(const float* __restrict__ x,
             const float* __restrict__ w1,
             const float* __restrict__ b1)
{
    __shared__ float  s_f[PROWS];          // 30x30, zero halo
    __shared__ float2 s_w[9 * 24];
    __shared__ float2 s_b2[24];

    const int frame = blockIdx.x;
    const int tid   = threadIdx.x;

    for (int i = tid; i < PROWS; i += 256) {
        const int r = i / PW, c = i - r * PW;
        float v = 0.f;
        if (r >= 1 && r <= HH && c >= 1 && c <= WW)
            v = x[frame * FRAME_PIX + (r - 1) * WW + (c - 1)];
        s_f[i] = v;
    }
    for (int i = tid; i < 9 * 24; i += 256) s_w[i] = ((const float2*)w1)[i];
    if (tid < 24) s_b2[tid] = ((const float2*)b1)[tid];
    __syncthreads();

    uint32_t* outp = (uint32_t*)(g_a1 + (size_t)frame * PROWS * FF);
    for (int idx = tid; idx < FRAME_PIX * 24; idx += 256) {
        const int p   = idx / 24;
        const int co2 = idx - p * 24;
        const int h   = p / WW;
        const int w   = p - h * WW;
        const int base = h * PW + w;
        float2 acc = s_b2[co2];
        #pragma unroll
        for (int dy = 0; dy < 3; ++dy) {
            #pragma unroll
            for (int dx = 0; dx < 3; ++dx) {
                const float v = s_f[base + dy * PW + dx];
                const float2 fw = s_w[(dy * 3 + dx) * 24 + co2];
                acc.x += v * fw.x;
                acc.y += v * fw.y;
            }
        }
        const __half2 hv = __floats2half2_rn(fmaxf(acc.x, 0.f), fmaxf(acc.y, 0.f));
        outp[((h + 1) * PW + (w + 1)) * 24 + co2] = *(const uint32_t*)&hv;
    }
}

// ---------------------------------------------------------------------------
// Kernel 2/3: persistent double-buffered conv48 via mma.sync (fp16, 1 pass).
// R11 config (proven 132 us/layer): 256 threads / 8 warps, T_PER_W=2,
// 2 CTAs/SM via quarter-frame items (smem 107 KB/CTA).
// ---------------------------------------------------------------------------
#define Q_ROWS    225
#define SLAB_ROWS 304
#define A_STRIDE  112
#define A_BYTES   (SLAB_ROWS * A_STRIDE)       // 34048
#define B_BYTES   (27 * 6 * 64 * 4)            // 41472
#define OFF_A0    0
#define OFF_A1    (OFF_A0 + A_BYTES)           // 34048
#define OFF_B     (OFF_A1 + A_BYTES)           // 68096
#define OFF_BI    (OFF_B + B_BYTES)            // 109568
#define CONV_SMEM (OFF_BI + FF * 4)            // 109760
#define MT_MAX    14
#define T_PER_W   2
#define GRID_CONV 296                          // 2 CTAs/SM x 148
#define N_ITEMS   (NFRAMES * 4)                // 4096 quarter-frames

__device__ __forceinline__ void issue_slab(uint32_t dst, const __half* __restrict__ in,
                                           int item, int tid)
{
    const int frame = item >> 2;
    const int rbase = (item & 3) * Q_ROWS;
    const char* src = (const char*)(in + (size_t)frame * PROWS * FF);
    for (int i = tid; i < SLAB_ROWS * 7; i += 256) {
        const int s   = i / 7;
        const int blk = i - s * 7;
        const int r   = rbase - 31 + s;
        bool valid = false;
        if (r >= 0 && r < PROWS && blk < 6) {
            const int rd = r / PW, rm = r - rd * PW;
            valid = (rd >= 1 && rd <= HH && rm >= 1 && rm <= WW);
        }
        const long off = valid ? ((long)r * 96 + blk * 16) : 0;
        cpa16(dst + s * A_STRIDE + blk * 16, src + off, valid ? 16u : 0u);
    }
}

template <int PHASE>
__global__ void __launch_bounds__(256, 2)
convmm_kernel(const __half* __restrict__ in,
              const uint32_t* __restrict__ bfrag,
              const float* __restrict__ bias)
{
    extern __shared__ __align__(16) char smem[];
    __shared__ float s_pool[8 * FF];

    const int bid  = blockIdx.x;
    const int tid  = threadIdx.x;
    const int wid  = tid >> 5;
    const int lane = tid & 31;
    const uint32_t smb = smem_u32(smem);
    const int nItems = (N_ITEMS - bid + GRID_CONV - 1) / GRID_CONV;

    float* s_bias = (float*)(smem + OFF_BI);
    if (tid < FF) s_bias[tid] = bias[tid];

    // Group 0: B fragments + first A slab
    for (int i = tid; i < B_BYTES / 16; i += 256)
        cpa16(smb + OFF_B + i * 16, (const char*)bfrag + i * 16, 16);
    if (nItems > 0) issue_slab(smb + OFF_A0, in, bid, tid);
    CPA_COMMIT();

    const uint32_t laneoff = (uint32_t)((lane & 15) * A_STRIDE + ((lane >> 4) << 4));
    const uint32_t* s_b = (const uint32_t*)(smem + OFF_B);

    for (int k = 0; k < nItems; ++k) {
        const int item  = bid + GRID_CONV * k;
        const int frame = item >> 2;
        const int rbase = (item & 3) * Q_ROWS;
        const uint32_t abuf = smb + ((k & 1) ? OFF_A1 : OFF_A0);

        if (k + 1 < nItems) {
            issue_slab(smb + ((k & 1) ? OFF_A0 : OFF_A1), in, item + GRID_CONV, tid);
            CPA_COMMIT();
            CPA_WAIT(1);
        } else {
            CPA_WAIT(0);
        }
        __syncthreads();

        int mtv[T_PER_W];
        uint32_t abase[T_PER_W];
        #pragma unroll
        for (int i = 0; i < T_PER_W; ++i) {
            int mt = wid + 8 * i;
            mtv[i] = mt;
            if (mt > MT_MAX) mt = MT_MAX;
            abase[i] = abuf + (uint32_t)((31 + mt * 16) * A_STRIDE) + laneoff;
        }

        float C[T_PER_W][6][4];
        #pragma unroll
        for (int i = 0; i < T_PER_W; ++i)
            #pragma unroll
            for (int nt = 0; nt < 6; ++nt) {
                C[i][nt][0] = 0.f; C[i][nt][1] = 0.f; C[i][nt][2] = 0.f; C[i][nt][3] = 0.f;
            }

        #pragma unroll 1
        for (int tap = 0; tap < 9; ++tap) {
            const int dy = tap / 3;
            const int aoff0 = ((dy - 1) * PW + (tap - dy * 3) - 1) * A_STRIDE;
            #pragma unroll
            for (int kc = 0; kc < 3; ++kc) {
                uint2 BW[6];
                const int bbase = ((tap * 3 + kc) * 6) * 64 + lane * 2;
                #pragma unroll
                for (int nt = 0; nt < 6; ++nt)
                    BW[nt] = *(const uint2*)(s_b + bbase + nt * 64);
                #pragma unroll
                for (int i = 0; i < T_PER_W; ++i) {
                    if (i == 0 || mtv[i] <= MT_MAX) {
                        uint32_t a[4];
                        ldmx4(a, abase[i] + (uint32_t)(aoff0 + kc * 32));
                        #pragma unroll
                        for (int nt = 0; nt < 6; ++nt)
                            mma_fp16(C[i][nt], a, BW[nt].x, BW[nt].y);
                    }
                }
            }
        }

        // ---- Epilogue ----
        float pool[6][2];
        if (PHASE == 1) {
            #pragma unroll
            for (int nt = 0; nt < 6; ++nt) { pool[nt][0] = 0.f; pool[nt][1] = 0.f; }
        }

        #pragma unroll
        for (int i = 0; i < T_PER_W; ++i) {
            if (mtv[i] > MT_MAX) continue;
            #pragma unroll
            for (int rh = 0; rh < 2; ++rh) {
                const int r = rbase + mtv[i] * 16 + (lane >> 2) + rh * 8;
                if (PHASE == 0) {
                    if (r < PROWS) {
                        uint32_t* d = (uint32_t*)(g_a2 + ((size_t)frame * PROWS + r) * FF);
                        #pragma unroll
                        for (int nt = 0; nt < 6; ++nt) {
                            const int co = nt * 8 + (lane & 3) * 2;
                            const __half h0 = __float2half_rn(fmaxf(C[i][nt][rh * 2]     + s_bias[co],     0.f));
                            const __half h1 = __float2half_rn(fmaxf(C[i][nt][rh * 2 + 1] + s_bias[co + 1], 0.f));
                            d[co >> 1] = (uint32_t)__half_as_ushort(h0) | ((uint32_t)__half_as_ushort(h1) << 16);
                        }
                    }
                } else {
                    bool valid = false;
                    if ((r - rbase) < Q_ROWS && r < PROWS) {
                        const int rd = r / PW, rm = r - rd * PW;
                        valid = (rd >= 1 && rd <= HH && rm >= 1 && rm <= WW);
                    }
                    if (valid) {
                        #pragma unroll
                        for (int nt = 0; nt < 6; ++nt) {
                            const int co = nt * 8 + (lane & 3) * 2;
                            pool[nt][0] += fmaxf(C[i][nt][rh * 2]     + s_bias[co],     0.f);
                            pool[nt][1] += fmaxf(C[i][nt][rh * 2 + 1] + s_bias[co + 1], 0.f);
                        }
                    }
                }
            }
        }

        if (PHASE == 1) {
            #pragma unroll
            for (int nt = 0; nt < 6; ++nt) {
                #pragma unroll
                for (int e = 0; e < 2; ++e) {
                    float v = pool[nt][e];
                    v += __shfl_xor_sync(0xffffffffu, v, 4);
                    v += __shfl_xor_sync(0xffffffffu, v, 8);
                    v += __shfl_xor_sync(0xffffffffu, v, 16);
                    if ((lane >> 2) == 0)
                        s_pool[wid * FF + nt * 8 + lane * 2 + e] = v;
                }
            }
            __syncthreads();
            if (tid < FF) {
                float s = 0.f;
                #pragma unroll
                for (int ww = 0; ww < 8; ++ww) s += s_pool[ww * FF + tid];
                g_feats[(frame * 4 + (item & 3)) * FF + tid] = s;
            }
        }
        __syncthreads();   // all reads of abuf done before it is refilled
    }
}

// ---------------------------------------------------------------------------
// Kernel 4: LSTM + BN2 + head. 128 threads/block: 4 warps parallelize the
// x-dot precompute (8 timesteps each); warp 0 runs the 8-term recurrence.
// (Measured ~8 us.)
// ---------------------------------------------------------------------------
__device__ __forceinline__ float fsig(float x)  { return __fdividef(1.f, 1.f + __expf(-x)); }
__device__ __forceinline__ float ftanh(float x) { return 1.f - __fdividef(2.f, __expf(2.f * x) + 1.f); }

__global__ void __launch_bounds__(128, 1)
lstm_kernel(const float* __restrict__ wf,  const float* __restrict__ bf,
            const float* __restrict__ wi1, const float* __restrict__ bi1,
            const float* __restrict__ wi2, const float* __restrict__ bi2,
            const float* __restrict__ wo,  const float* __restrict__ bo,
            const float* __restrict__ bn1_g, const float* __restrict__ bn1_b,
            const float* __restrict__ bn1_m, const float* __restrict__ bn1_v,
            const float* __restrict__ bn2_g, const float* __restrict__ bn2_b,
            const float* __restrict__ bn2_m, const float* __restrict__ bn2_v,
            const float* __restrict__ w_out, const float* __restrict__ b_out,
            float* __restrict__ out)
{
    __shared__ float s_x[TT][FF];
    __shared__ float s_g[TT][32];
    __shared__ float s_sc1[FF], s_sh1[FF];

    const int b    = blockIdx.x;
    const int tid  = threadIdx.x;
    const int wrp  = tid >> 5;
    const int lane = tid & 31;
    const int u    = lane & 7;

    const float* Wg = (lane < 8) ? wf : (lane < 16) ? wi1 : (lane < 24) ? wi2 : wo;
    const float* Bg = (lane < 8) ? bf : (lane < 16) ? bi1 : (lane < 24) ? bi2 : bo;
    float wcol[FF + UU];
    #pragma unroll
    for (int k = 0; k < FF + UU; ++k) wcol[k] = Wg[k * UU + u];
    const float bgate = Bg[u];

    for (int co = tid; co < FF; co += 128) {
        const float sc = bn1_g[co] * rsqrtf(bn1_v[co] + EPSB);
        s_sc1[co] = sc * (1.f / (float)FRAME_PIX);
        s_sh1[co] = bn1_b[co] - bn1_m[co] * sc;
    }
    __syncthreads();

    for (int i = tid; i < TT * FF; i += 128) {
        const int t = i / FF, co = i - t * FF;
        const int fr = (b << 5) + t;
        const float ps = g_feats[(fr * 4 + 0) * FF + co] + g_feats[(fr * 4 + 1) * FF + co]
                       + g_feats[(fr * 4 + 2) * FF + co] + g_feats[(fr * 4 + 3) * FF + co];
        s_x[t][co] = ps * s_sc1[co] + s_sh1[co];
    }
    __syncthreads();

    #pragma unroll
    for (int tt = 0; tt < 8; ++tt) {
        const int t = wrp * 8 + tt;
        float a0 = 0.f, a1 = 0.f, a2 = 0.f, a3 = 0.f;
        #pragma unroll
        for (int k = 0; k < FF; k += 4) {
            a0 += s_x[t][k]     * wcol[k];
            a1 += s_x[t][k + 1] * wcol[k + 1];
            a2 += s_x[t][k + 2] * wcol[k + 2];
            a3 += s_x[t][k + 3] * wcol[k + 3];
        }
        s_g[t][lane] = bgate + ((a0 + a1) + (a2 + a3));
    }
    __syncthreads();

    if (wrp == 0) {
        const float sc2  = bn2_g[u] * rsqrtf(bn2_v[u] + EPSB);
        const float coef = sc2 * w_out[u];
        float outc = b_out[0];
        #pragma unroll
        for (int j = 0; j < UU; ++j) {
            const float s2 = bn2_g[j] * rsqrtf(bn2_v[j] + EPSB);
            outc += (bn2_b[j] - bn2_m[j] * s2) * w_out[j];
        }

        float c = 0.f, h = 0.f;
        for (int t = 0; t < TT; ++t) {
            float a = s_g[t][lane];
            #pragma unroll
            for (int j = 0; j < UU; ++j)
                a += __shfl_sync(0xffffffffu, h, j) * wcol[FF + j];

            const float fg = fsig (__shfl_sync(0xffffffffu, a, u));
            const float ig = fsig (__shfl_sync(0xffffffffu, a, u + 8));
            const float gg = ftanh(__shfl_sync(0xffffffffu, a, u + 16));
            const float og = fsig (__shfl_sync(0xffffffffu, a, u + 24));
            c = fg * c + ig * gg;
            h = og * ftanh(c);

            float p = h * coef;
            p += __shfl_xor_sync(0xffffffffu, p, 1);
            p += __shfl_xor_sync(0xffffffffu, p, 2);
            p += __shfl_xor_sync(0xffffffffu, p, 4);
            if (lane == 0) out[(b << 5) + t] = p + outc;
        }
    }
}

// ---------------------------------------------------------------------------
// Launch
// ---------------------------------------------------------------------------
extern "C" void kernel_launch(void* const* d_in, const int* in_sizes, int n_in,
                              void* d_out, int out_size)
{
    const float* x     = (const float*)d_in[0];
    const float* w1    = (const float*)d_in[1];
    const float* b1    = (const float*)d_in[2];
    const float* w2    = (const float*)d_in[3];
    const float* b2    = (const float*)d_in[4];
    const float* w3    = (const float*)d_in[5];
    const float* b3    = (const float*)d_in[6];
    const float* bn1_g = (const float*)d_in[7];
    const float* bn1_b = (const float*)d_in[8];
    const float* bn1_m = (const float*)d_in[9];
    const float* bn1_v = (const float*)d_in[10];
    const float* wf    = (const float*)d_in[11];
    const float* bf    = (const float*)d_in[12];
    const float* wi1   = (const float*)d_in[13];
    const float* bi1   = (const float*)d_in[14];
    const float* wi2   = (const float*)d_in[15];
    const float* bi2   = (const float*)d_in[16];
    const float* wo    = (const float*)d_in[17];
    const float* bo    = (const float*)d_in[18];
    const float* bn2_g = (const float*)d_in[19];
    const float* bn2_b = (const float*)d_in[20];
    const float* bn2_m = (const float*)d_in[21];
    const float* bn2_v = (const float*)d_in[22];
    const float* w_out = (const float*)d_in[23];
    const float* b_out = (const float*)d_in[24];
    float* out = (float*)d_out;

    cudaFuncSetAttribute(convmm_kernel<0>, cudaFuncAttributeMaxDynamicSharedMemorySize, CONV_SMEM);
    cudaFuncSetAttribute(convmm_kernel<1>, cudaFuncAttributeMaxDynamicSharedMemorySize, CONV_SMEM);

    __half *a1 = nullptr, *a2 = nullptr;
    uint32_t* bfrag = nullptr;
    cudaGetSymbolAddress((void**)&a1, g_a1);
    cudaGetSymbolAddress((void**)&a2, g_a2);
    cudaGetSymbolAddress((void**)&bfrag, g_bfrag);

    prep_kernel<<<2, 256>>>(w2, w3);
    conv1_kernel<<<NFRAMES, 256>>>(x, w1, b1);
    convmm_kernel<0><<<GRID_CONV, 256, CONV_SMEM>>>(a1, bfrag, b2);
    convmm_kernel<1><<<GRID_CONV, 256, CONV_SMEM>>>(a2, bfrag + 27 * 6 * 64, b3);
    lstm_kernel<<<BB, 128>>>(wf, bf, wi1, bi1, wi2, bi2, wo, bo,
                             bn1_g, bn1_b, bn1_m, bn1_v,
                             bn2_g, bn2_b, bn2_m, bn2_v,
                             w_out, b_out, out);
}

// round 17
// speedup vs baseline: 1.1372x; 1.0186x over previous
#include <cuda_runtime.h>
#include <cuda_fp16.h>
#include <cstdint>
#include <math.h>

// Problem constants
#define BB   32
#define TT   32
#define HH   28
#define WW   28
#define FF   48
#define UU   8
#define EPSB 1e-3f
#define NFRAMES (BB*TT)            // 1024
#define FRAME_PIX (HH*WW)          // 784
#define PW   30                    // padded width
#define PROWS (PW*PW)              // 900 padded pixel-rows per frame

// ---------------------------------------------------------------------------
// Warp-MMA helpers
// ---------------------------------------------------------------------------
__device__ __forceinline__ uint32_t smem_u32(const void* p) {
    return (uint32_t)__cvta_generic_to_shared(p);
}
__device__ __forceinline__ void ldmx4(uint32_t a[4], uint32_t addr) {
    asm volatile("ldmatrix.sync.aligned.m8n8.x4.shared.b16 {%0,%1,%2,%3}, [%4];"
                 : "=r"(a[0]), "=r"(a[1]), "=r"(a[2]), "=r"(a[3]) : "r"(addr));
}
__device__ __forceinline__ void mma_fp16(float c[4], const uint32_t a[4],
                                         uint32_t b0, uint32_t b1) {
    asm volatile("mma.sync.aligned.m16n8k16.row.col.f32.f16.f16.f32 "
                 "{%0,%1,%2,%3},{%4,%5,%6,%7},{%8,%9},{%0,%1,%2,%3};"
                 : "+f"(c[0]), "+f"(c[1]), "+f"(c[2]), "+f"(c[3])
                 : "r"(a[0]), "r"(a[1]), "r"(a[2]), "r"(a[3]), "r"(b0), "r"(b1));
}
__device__ __forceinline__ void cpa16(uint32_t dst, const void* src, uint32_t srcbytes) {
    asm volatile("cp.async.cg.shared.global [%0], [%1], 16, %2;"
                 :: "r"(dst), "l"(src), "r"(srcbytes));
}
#define CPA_COMMIT() asm volatile("cp.async.commit_group;" ::: "memory")
#define CPA_WAIT(n)  asm volatile("cp.async.wait_group %0;" :: "n"(n) : "memory")

__device__ __forceinline__ float fsig(float x)  { return __fdividef(1.f, 1.f + __expf(-x)); }
__device__ __forceinline__ float ftanh(float x) { return 1.f - __fdividef(2.f, __expf(2.f * x) + 1.f); }

// ---------------------------------------------------------------------------
// Scratch
// ---------------------------------------------------------------------------
__device__ __align__(16) __half g_a1[NFRAMES * PROWS * FF];
__device__ __align__(16) __half g_a2[NFRAMES * PROWS * FF];
__device__ __align__(16) uint32_t g_bfrag[2][27 * 6 * 64];  // fp16x2 fragments
__device__ float g_feats[NFRAMES * 4 * FF];   // per-(frame,quarter) pooled partials
__device__ int g_done = 0;                    // convmm<1> completion tickets
__device__ int g_fin  = 0;                    // finished lstm CTAs

// ---------------------------------------------------------------------------
// Kernel 1: conv1 (C=1 -> 48) + ReLU, with prep (weight fragmenting) merged
// into the same grid: blocks 1024/1025 build the B fragments for w2/w3.
// ---------------------------------------------------------------------------
__global__ void __launch_bounds__(256, 1)
conv1_prep_kernel(const float* __restrict__ x,
                  const float* __restrict__ w1,
                  const float* __restrict__ b1,
                  const float* __restrict__ w2,
                  const float* __restrict__ w3)
{
    const int tid = threadIdx.x;

    if (blockIdx.x >= NFRAMES) {
        // ---- prep body ----
        const int which = blockIdx.x - NFRAMES;         // 0 -> w2, 1 -> w3
        const float* w = which == 0 ? w2 : w3;
        uint32_t* dst = g_bfrag[which];
        for (int i = tid; i < 162 * 64; i += 256) {
            const int group = i >> 6;
            const int slot  = i & 63;
            const int l     = slot >> 1;
            const int reg   = slot & 1;
            const int tapkc = group / 6;
            const int nt    = group - tapkc * 6;
            const int tap   = tapkc / 3;
            const int kc    = tapkc - tap * 3;
            const int n     = nt * 8 + (l >> 2);
            const int k     = kc * 16 + (l & 3) * 2 + reg * 8;
            const __half h0 = __float2half_rn(w[(tap * FF + k)     * FF + n]);
            const __half h1 = __float2half_rn(w[(tap * FF + k + 1) * FF + n]);
            dst[i] = (uint32_t)__half_as_ushort(h0) | ((uint32_t)__half_as_ushort(h1) << 16);
        }
        return;
    }

    // ---- conv1 body (R11 co-pair version, measured fastest) ----
    __shared__ float  s_f[PROWS];          // 30x30, zero halo
    __shared__ float2 s_w[9 * 24];
    __shared__ float2 s_b2[24];

    const int frame = blockIdx.x;

    for (int i = tid; i < PROWS; i += 256) {
        const int r = i / PW, c = i - r * PW;
        float v = 0.f;
        if (r >= 1 && r <= HH && c >= 1 && c <= WW)
            v = x[frame * FRAME_PIX + (r - 1) * WW + (c - 1)];
        s_f[i] = v;
    }
    for (int i = tid; i < 9 * 24; i += 256) s_w[i] = ((const float2*)w1)[i];
    if (tid < 24) s_b2[tid] = ((const float2*)b1)[tid];
    __syncthreads();

    uint32_t* outp = (uint32_t*)(g_a1 + (size_t)frame * PROWS * FF);
    for (int idx = tid; idx < FRAME_PIX * 24; idx += 256) {
        const int p   = idx / 24;
        const int co2 = idx - p * 24;
        const int h   = p / WW;
        const int w   = p - h * WW;
        const int base = h * PW + w;
        float2 acc = s_b2[co2];
        #pragma unroll
        for (int dy = 0; dy < 3; ++dy) {
            #pragma unroll
            for (int dx = 0; dx < 3; ++dx) {
                const float v = s_f[base + dy * PW + dx];
                const float2 fw = s_w[(dy * 3 + dx) * 24 + co2];
                acc.x += v * fw.x;
                acc.y += v * fw.y;
            }
        }
        const __half2 hv = __floats2half2_rn(fmaxf(acc.x, 0.f), fmaxf(acc.y, 0.f));
        outp[((h + 1) * PW + (w + 1)) * 24 + co2] = *(const uint32_t*)&hv;
    }
}

// ---------------------------------------------------------------------------
// conv48 geometry (quarter-frame items) — R11 proven config
// ---------------------------------------------------------------------------
#define Q_ROWS    225
#define SLAB_ROWS 304
#define A_STRIDE  112
#define A_BYTES   (SLAB_ROWS * A_STRIDE)       // 34048
#define B_BYTES   (27 * 6 * 64 * 4)            // 41472
#define OFF_A0    0
#define OFF_A1    (OFF_A0 + A_BYTES)           // 34048
#define OFF_B     (OFF_A1 + A_BYTES)           // 68096
#define OFF_BI    (OFF_B + B_BYTES)            // 109568
#define CONV_SMEM (OFF_BI + FF * 4)            // 109760
#define MT_MAX    14
#define T_PER_W   2
#define GRID_CONV 296                          // 2 CTAs/SM x 148
#define N_ITEMS   (NFRAMES * 4)                // 4096 quarter-frames

__device__ __forceinline__ void issue_slab(uint32_t dst, const __half* __restrict__ in,
                                           int item, int tid)
{
    const int frame = item >> 2;
    const int rbase = (item & 3) * Q_ROWS;
    const char* src = (const char*)(in + (size_t)frame * PROWS * FF);
    for (int i = tid; i < SLAB_ROWS * 7; i += 256) {
        const int s   = i / 7;
        const int blk = i - s * 7;
        const int r   = rbase - 31 + s;
        bool valid = false;
        if (r >= 0 && r < PROWS && blk < 6) {
            const int rd = r / PW, rm = r - rd * PW;
            valid = (rd >= 1 && rd <= HH && rm >= 1 && rm <= WW);
        }
        const long off = valid ? ((long)r * 96 + blk * 16) : 0;
        cpa16(dst + s * A_STRIDE + blk * 16, src + off, valid ? 16u : 0u);
    }
}

// Shared mainloop body for both phases, returning via epilogue lambda-like
// duplication. PHASE 0: store to g_a2. PHASE 1: pool into g_feats.
template <int PHASE>
__device__ __forceinline__ void convmm_body(const __half* __restrict__ in,
                                            const uint32_t* __restrict__ bfrag,
                                            const float* __restrict__ bias,
                                            char* smem, float* s_pool,
                                            int bid, int tid)
{
    const int wid  = tid >> 5;
    const int lane = tid & 31;
    const uint32_t smb = smem_u32(smem);
    const int nItems = (N_ITEMS - bid + GRID_CONV - 1) / GRID_CONV;

    float* s_bias = (float*)(smem + OFF_BI);
    if (tid < FF) s_bias[tid] = bias[tid];

    for (int i = tid; i < B_BYTES / 16; i += 256)
        cpa16(smb + OFF_B + i * 16, (const char*)bfrag + i * 16, 16);
    if (nItems > 0) issue_slab(smb + OFF_A0, in, bid, tid);
    CPA_COMMIT();

    const uint32_t laneoff = (uint32_t)((lane & 15) * A_STRIDE + ((lane >> 4) << 4));
    const uint32_t* s_b = (const uint32_t*)(smem + OFF_B);

    for (int k = 0; k < nItems; ++k) {
        const int item  = bid + GRID_CONV * k;
        const int frame = item >> 2;
        const int rbase = (item & 3) * Q_ROWS;
        const uint32_t abuf = smb + ((k & 1) ? OFF_A1 : OFF_A0);

        if (k + 1 < nItems) {
            issue_slab(smb + ((k & 1) ? OFF_A0 : OFF_A1), in, item + GRID_CONV, tid);
            CPA_COMMIT();
            CPA_WAIT(1);
        } else {
            CPA_WAIT(0);
        }
        __syncthreads();

        int mtv[T_PER_W];
        uint32_t abase[T_PER_W];
        #pragma unroll
        for (int i = 0; i < T_PER_W; ++i) {
            int mt = wid + 8 * i;
            mtv[i] = mt;
            if (mt > MT_MAX) mt = MT_MAX;
            abase[i] = abuf + (uint32_t)((31 + mt * 16) * A_STRIDE) + laneoff;
        }

        float C[T_PER_W][6][4];
        #pragma unroll
        for (int i = 0; i < T_PER_W; ++i)
            #pragma unroll
            for (int nt = 0; nt < 6; ++nt) {
                C[i][nt][0] = 0.f; C[i][nt][1] = 0.f; C[i][nt][2] = 0.f; C[i][nt][3] = 0.f;
            }

        #pragma unroll 1
        for (int tap = 0; tap < 9; ++tap) {
            const int dy = tap / 3;
            const int aoff0 = ((dy - 1) * PW + (tap - dy * 3) - 1) * A_STRIDE;
            #pragma unroll
            for (int kc = 0; kc < 3; ++kc) {
                uint2 BW[6];
                const int bbase = ((tap * 3 + kc) * 6) * 64 + lane * 2;
                #pragma unroll
                for (int nt = 0; nt < 6; ++nt)
                    BW[nt] = *(const uint2*)(s_b + bbase + nt * 64);
                #pragma unroll
                for (int i = 0; i < T_PER_W; ++i) {
                    if (i == 0 || mtv[i] <= MT_MAX) {
                        uint32_t a[4];
                        ldmx4(a, abase[i] + (uint32_t)(aoff0 + kc * 32));
                        #pragma unroll
                        for (int nt = 0; nt < 6; ++nt)
                            mma_fp16(C[i][nt], a, BW[nt].x, BW[nt].y);
                    }
                }
            }
        }

        float pool[6][2];
        if (PHASE == 1) {
            #pragma unroll
            for (int nt = 0; nt < 6; ++nt) { pool[nt][0] = 0.f; pool[nt][1] = 0.f; }
        }

        #pragma unroll
        for (int i = 0; i < T_PER_W; ++i) {
            if (mtv[i] > MT_MAX) continue;
            #pragma unroll
            for (int rh = 0; rh < 2; ++rh) {
                const int r = rbase + mtv[i] * 16 + (lane >> 2) + rh * 8;
                if (PHASE == 0) {
                    if (r < PROWS) {
                        uint32_t* d = (uint32_t*)(g_a2 + ((size_t)frame * PROWS + r) * FF);
                        #pragma unroll
                        for (int nt = 0; nt < 6; ++nt) {
                            const int co = nt * 8 + (lane & 3) * 2;
                            const __half h0 = __float2half_rn(fmaxf(C[i][nt][rh * 2]     + s_bias[co],     0.f));
                            const __half h1 = __float2half_rn(fmaxf(C[i][nt][rh * 2 + 1] + s_bias[co + 1], 0.f));
                            d[co >> 1] = (uint32_t)__half_as_ushort(h0) | ((uint32_t)__half_as_ushort(h1) << 16);
                        }
                    }
                } else {
                    bool valid = false;
                    if ((r - rbase) < Q_ROWS && r < PROWS) {
                        const int rd = r / PW, rm = r - rd * PW;
                        valid = (rd >= 1 && rd <= HH && rm >= 1 && rm <= WW);
                    }
                    if (valid) {
                        #pragma unroll
                        for (int nt = 0; nt < 6; ++nt) {
                            const int co = nt * 8 + (lane & 3) * 2;
                            pool[nt][0] += fmaxf(C[i][nt][rh * 2]     + s_bias[co],     0.f);
                            pool[nt][1] += fmaxf(C[i][nt][rh * 2 + 1] + s_bias[co + 1], 0.f);
                        }
                    }
                }
            }
        }

        if (PHASE == 1) {
            #pragma unroll
            for (int nt = 0; nt < 6; ++nt) {
                #pragma unroll
                for (int e = 0; e < 2; ++e) {
                    float v = pool[nt][e];
                    v += __shfl_xor_sync(0xffffffffu, v, 4);
                    v += __shfl_xor_sync(0xffffffffu, v, 8);
                    v += __shfl_xor_sync(0xffffffffu, v, 16);
                    if ((lane >> 2) == 0)
                        s_pool[wid * FF + nt * 8 + lane * 2 + e] = v;
                }
            }
            __syncthreads();
            if (tid < FF) {
                float s = 0.f;
                #pragma unroll
                for (int ww = 0; ww < 8; ++ww) s += s_pool[ww * FF + tid];
                g_feats[(frame * 4 + (item & 3)) * FF + tid] = s;
            }
        }
        __syncthreads();
    }
}

// Phase 0: conv2 (writes g_a2)
__global__ void __launch_bounds__(256, 2)
convmm_store(const __half* __restrict__ in,
             const uint32_t* __restrict__ bfrag,
             const float* __restrict__ bias)
{
    extern __shared__ __align__(16) char smem[];
    convmm_body<0>(in, bfrag, bias, smem, nullptr, blockIdx.x, threadIdx.x);
}

// Phase 1: conv3 + pool, with LSTM fused as tail CTAs.
// After the main loop, each CTA takes a ticket; the last 32 ticket-holders
// each run one batch element's LSTM after spinning for full completion.
__global__ void __launch_bounds__(256, 2)
convmm_pool_lstm(const __half* __restrict__ in,
                 const uint32_t* __restrict__ bfrag,
                 const float* __restrict__ bias,
                 const float* __restrict__ wf,  const float* __restrict__ bf,
                 const float* __restrict__ wi1, const float* __restrict__ bi1,
                 const float* __restrict__ wi2, const float* __restrict__ bi2,
                 const float* __restrict__ wo,  const float* __restrict__ bo,
                 const float* __restrict__ bn1_g, const float* __restrict__ bn1_b,
                 const float* __restrict__ bn1_m, const float* __restrict__ bn1_v,
                 const float* __restrict__ bn2_g, const float* __restrict__ bn2_b,
                 const float* __restrict__ bn2_m, const float* __restrict__ bn2_v,
                 const float* __restrict__ w_out, const float* __restrict__ b_out,
                 float* __restrict__ out)
{
    extern __shared__ __align__(16) char smem[];
    __shared__ float s_pool[8 * FF];
    __shared__ int s_pos;

    const int tid = threadIdx.x;

    convmm_body<1>(in, bfrag, bias, smem, s_pool, blockIdx.x, tid);

    // ---- ticket ----
    __threadfence();
    if (tid == 0) s_pos = atomicAdd(&g_done, 1);
    __syncthreads();
    const int pos = s_pos;
    if (pos < GRID_CONV - BB) return;          // not a tail CTA
    const int b = pos - (GRID_CONV - BB);      // batch element 0..31

    // ---- wait for all CTAs' g_feats writes ----
    if (tid == 0) {
        while (atomicAdd(&g_done, 0) < GRID_CONV)
            __nanosleep(64);
    }
    __syncthreads();
    __threadfence();

    // ---- LSTM for batch b (reuse smem region) ----
    float* s_x   = (float*)smem;                       // [TT][FF]
    float* s_g   = s_x + TT * FF;                      // [TT][32]
    float* s_sc1 = s_g + TT * 32;                      // [FF]
    float* s_sh1 = s_sc1 + FF;                         // [FF]

    const int wrp  = tid >> 5;
    const int lane = tid & 31;
    const int u    = lane & 7;

    const float* Wg = (lane < 8) ? wf : (lane < 16) ? wi1 : (lane < 24) ? wi2 : wo;
    const float* Bg = (lane < 8) ? bf : (lane < 16) ? bi1 : (lane < 24) ? bi2 : bo;
    float wcol[FF + UU];
    #pragma unroll
    for (int k = 0; k < FF + UU; ++k) wcol[k] = Wg[k * UU + u];
    const float bgate = Bg[u];

    for (int co = tid; co < FF; co += 256) {
        const float sc = bn1_g[co] * rsqrtf(bn1_v[co] + EPSB);
        s_sc1[co] = sc * (1.f / (float)FRAME_PIX);
        s_sh1[co] = bn1_b[co] - bn1_m[co] * sc;
    }
    __syncthreads();

    for (int i = tid; i < TT * FF; i += 256) {
        const int t = i / FF, co = i - t * FF;
        const int fr = (b << 5) + t;
        const float ps = g_feats[(fr * 4 + 0) * FF + co] + g_feats[(fr * 4 + 1) * FF + co]
                       + g_feats[(fr * 4 + 2) * FF + co] + g_feats[(fr * 4 + 3) * FF + co];
        s_x[t * FF + co] = ps * s_sc1[co] + s_sh1[co];
    }
    __syncthreads();

    // 8 warps precompute x-dots: warp w handles t = w*4 .. w*4+3
    #pragma unroll
    for (int tt = 0; tt < 4; ++tt) {
        const int t = wrp * 4 + tt;
        float a0 = 0.f, a1 = 0.f, a2 = 0.f, a3 = 0.f;
        #pragma unroll
        for (int k = 0; k < FF; k += 4) {
            a0 += s_x[t * FF + k]     * wcol[k];
            a1 += s_x[t * FF + k + 1] * wcol[k + 1];
            a2 += s_x[t * FF + k + 2] * wcol[k + 2];
            a3 += s_x[t * FF + k + 3] * wcol[k + 3];
        }
        s_g[t * 32 + lane] = bgate + ((a0 + a1) + (a2 + a3));
    }
    __syncthreads();

    if (wrp == 0) {
        const float sc2  = bn2_g[u] * rsqrtf(bn2_v[u] + EPSB);
        const float coef = sc2 * w_out[u];
        float outc = b_out[0];
        #pragma unroll
        for (int j = 0; j < UU; ++j) {
            const float s2 = bn2_g[j] * rsqrtf(bn2_v[j] + EPSB);
            outc += (bn2_b[j] - bn2_m[j] * s2) * w_out[j];
        }

        float c = 0.f, h = 0.f;
        for (int t = 0; t < TT; ++t) {
            float a = s_g[t * 32 + lane];
            #pragma unroll
            for (int j = 0; j < UU; ++j)
                a += __shfl_sync(0xffffffffu, h, j) * wcol[FF + j];

            const float fg = fsig (__shfl_sync(0xffffffffu, a, u));
            const float ig = fsig (__shfl_sync(0xffffffffu, a, u + 8));
            const float gg = ftanh(__shfl_sync(0xffffffffu, a, u + 16));
            const float og = fsig (__shfl_sync(0xffffffffu, a, u + 24));
            c = fg * c + ig * gg;
            h = og * ftanh(c);

            float p = h * coef;
            p += __shfl_xor_sync(0xffffffffu, p, 1);
            p += __shfl_xor_sync(0xffffffffu, p, 2);
            p += __shfl_xor_sync(0xffffffffu, p, 4);
            if (lane == 0) out[(b << 5) + t] = p + outc;
        }
    }

    // ---- reset counters for next graph replay ----
    __syncthreads();
    if (tid == 0) {
        const int fin = atomicAdd(&g_fin, 1);
        if (fin == BB - 1) {        // last lstm CTA: everyone else is done
            g_fin  = 0;
            g_done = 0;
            __threadfence();
        }
    }
}

// ---------------------------------------------------------------------------
// Launch
// ---------------------------------------------------------------------------
extern "C" void kernel_launch(void* const* d_in, const int* in_sizes, int n_in,
                              void* d_out, int out_size)
{
    const float* x     = (const float*)d_in[0];
    const float* w1    = (const float*)d_in[1];
    const float* b1    = (const float*)d_in[2];
    const float* w2    = (const float*)d_in[3];
    const float* b2    = (const float*)d_in[4];
    const float* w3    = (const float*)d_in[5];
    const float* b3    = (const float*)d_in[6];
    const float* bn1_g = (const float*)d_in[7];
    const float* bn1_b = (const float*)d_in[8];
    const float* bn1_m = (const float*)d_in[9];
    const float* bn1_v = (const float*)d_in[10];
    const float* wf    = (const float*)d_in[11];
    const float* bf    = (const float*)d_in[12];
    const float* wi1   = (const float*)d_in[13];
    const float* bi1   = (const float*)d_in[14];
    const float* wi2   = (const float*)d_in[15];
    const float* bi2   = (const float*)d_in[16];
    const float* wo    = (const float*)d_in[17];
    const float* bo    = (const float*)d_in[18];
    const float* bn2_g = (const float*)d_in[19];
    const float* bn2_b = (const float*)d_in[20];
    const float* bn2_m = (const float*)d_in[21];
    const float* bn2_v = (const float*)d_in[22];
    const float* w_out = (const float*)d_in[23];
    const float* b_out = (const float*)d_in[24];
    float* out = (float*)d_out;

    cudaFuncSetAttribute(convmm_store,     cudaFuncAttributeMaxDynamicSharedMemorySize, CONV_SMEM);
    cudaFuncSetAttribute(convmm_pool_lstm, cudaFuncAttributeMaxDynamicSharedMemorySize, CONV_SMEM);

    __half *a1 = nullptr, *a2 = nullptr;
    uint32_t* bfrag = nullptr;
    cudaGetSymbolAddress((void**)&a1, g_a1);
    cudaGetSymbolAddress((void**)&a2, g_a2);
    cudaGetSymbolAddress((void**)&bfrag, g_bfrag);

    conv1_prep_kernel<<<NFRAMES + 2, 256>>>(x, w1, b1, w2, w3);
    convmm_store<<<GRID_CONV, 256, CONV_SMEM>>>(a1, bfrag, b2);
    convmm_pool_lstm<<<GRID_CONV, 256, CONV_SMEM>>>(a2, bfrag + 27 * 6 * 64, b3,
                                                    wf, bf, wi1, bi1, wi2, bi2, wo, bo,
                                                    bn1_g, bn1_b, bn1_m, bn1_v,
                                                    bn2_g, bn2_b, bn2_m, bn2_v,
                                                    w_out, b_out, out);
}